// round 15
// baseline (speedup 1.0000x reference)
#include <cuda_runtime.h>
#include <cuda_bf16.h>
#include <cuda_fp16.h>
#include <cstdint>

#define BB  4
#define NN  2048
#define FIN 256
#define HH  8
#define DD  32
#define NW  (NN/32)   // 64 adj words per row

// ---------------- device scratch (no allocations allowed) ----------------
__device__ float    g_Wh[BB*HH*NN*DD];       // [b][h][n][d] f32 (for k_ee)
__device__ uint32_t g_WhT[BB*HH*DD*NN/2];    // [b][h][d][j] fp16 pairs (for k_attn B)
__device__ float2   g_AI2[BB*HH*NN];         // (A1, A2) per row i
__device__ uint32_t g_E12[BB*HH*NN];         // per j-pair: {E1 f16x2, E2 f16x2} interleaved
__device__ unsigned g_adj[BB*NN*NW];         // packed adjacency bits, TRANSPOSED [b][jw][i]

// ---------------- mma.sync / packed helpers (portable PTX) ----------------
__device__ __forceinline__ void mma_bf16(float* c,
                                         uint32_t a0, uint32_t a1, uint32_t a2, uint32_t a3,
                                         uint32_t b0, uint32_t b1) {
    asm volatile(
        "mma.sync.aligned.m16n8k16.row.col.f32.bf16.bf16.f32 "
        "{%0,%1,%2,%3}, {%4,%5,%6,%7}, {%8,%9}, {%0,%1,%2,%3};"
        : "+f"(c[0]), "+f"(c[1]), "+f"(c[2]), "+f"(c[3])
        : "r"(a0), "r"(a1), "r"(a2), "r"(a3), "r"(b0), "r"(b1));
}
__device__ __forceinline__ void mma_f16(float* c,
                                        uint32_t a0, uint32_t a1, uint32_t a2, uint32_t a3,
                                        uint32_t b0, uint32_t b1) {
    asm volatile(
        "mma.sync.aligned.m16n8k16.row.col.f32.f16.f16.f32 "
        "{%0,%1,%2,%3}, {%4,%5,%6,%7}, {%8,%9}, {%0,%1,%2,%3};"
        : "+f"(c[0]), "+f"(c[1]), "+f"(c[2]), "+f"(c[3])
        : "r"(a0), "r"(a1), "r"(a2), "r"(a3), "r"(b0), "r"(b1));
}
__device__ __forceinline__ uint32_t bfpack(float lo, float hi) {
    uint32_t r;
    asm("cvt.rn.bf16x2.f32 %0, %1, %2;" : "=r"(r) : "f"(hi), "f"(lo));
    return r;
}
__device__ __forceinline__ uint32_t h2pack(float lo, float hi) {
    uint32_t r;
    asm("cvt.rn.f16x2.f32 %0, %1, %2;" : "=r"(r) : "f"(hi), "f"(lo));
    return r;
}
__device__ __forceinline__ float bfround(float v) {
    return __bfloat162float(__float2bfloat16(v));
}
__device__ __forceinline__ uint32_t hmul2(uint32_t a, uint32_t b) {
    uint32_t r;
    asm("mul.f16x2 %0, %1, %2;" : "=r"(r) : "r"(a), "r"(b));
    return r;
}
__device__ __forceinline__ uint32_t hmax2(uint32_t a, uint32_t b) {
    uint32_t r;
    asm("max.f16x2 %0, %1, %2;" : "=r"(r) : "r"(a), "r"(b));
    return r;
}
// mask word for adjacency bits k,k+1: 0xFFFF per set halfword
__device__ __forceinline__ uint32_t mask2(uint32_t word, int k) {
    uint32_t t0, t1;
    asm("bfe.u32 %0, %1, %2, 1;" : "=r"(t0) : "r"(word), "r"(k));
    asm("bfe.u32 %0, %1, %2, 1;" : "=r"(t1) : "r"(word), "r"(k + 1));
    return t0 * 0x0000FFFFu + t1 * 0xFFFF0000u;
}
#define CP_ASYNC16(dst32, src) \
    asm volatile("cp.async.cg.shared.global [%0], [%1], 16;" :: "r"(dst32), "l"(src) : "memory")
#define CP_COMMIT() asm volatile("cp.async.commit_group;" ::: "memory")
#define CP_WAIT1()  asm volatile("cp.async.wait_group 1;" ::: "memory")

// ---------------- kernel 1: pack adjacency to bits (transposed) ----------------
__global__ __launch_bounds__(256) void k_pack(const int* __restrict__ adj) {
    const int nwarps = (gridDim.x * blockDim.x) >> 5;
    const int wid    = (blockIdx.x * blockDim.x + threadIdx.x) >> 5;
    const int lane   = threadIdx.x & 31;
    const int total  = BB*NN*NW;
    for (int w = wid; w < total; w += nwarps) {
        int v = adj[(size_t)w * 32 + lane];
        unsigned m = __ballot_sync(0xffffffffu, v != 0);
        if (lane == 0) {
            int b  = w / (NN*NW);
            int r  = w - b * (NN*NW);
            int i  = r / NW;
            int jw = r - i * NW;
            g_adj[((size_t)b * NW + jw) * NN + i] = m;
        }
    }
}

// ---------------- kernel 2: Wh = x @ W via 3xBF16 mma.sync (near-fp32) ----------------
// Writes g_Wh (f32, for k_ee) and g_WhT (fp16 transposed [d][j], for k_attn).
__global__ __launch_bounds__(256) void k_gemm1(const float* __restrict__ x,
                                               const float* __restrict__ W) {
    __shared__ uint32_t sAh[128*12], sAl[128*12];
    __shared__ uint32_t sBh[8*136],  sBl[8*136];
    const int t    = threadIdx.x;
    const int lane = t & 31;
    const int wid  = t >> 5;
    const int g    = lane >> 2;
    const int tig  = lane & 3;
    const int wy   = wid & 3;
    const int wx   = wid >> 2;
    const int rb   = blockIdx.y * 128;
    const int cb   = blockIdx.x * 128;

    const int row_a = t >> 1;
    const int kb_a  = (t & 1) * 8;
    const int col_b = t & 127;
    const int kb_b  = (t >> 7) * 8;
    const int col_g = cb + col_b;
    const float* wp = W + (size_t)(col_g >> 5) * (FIN*DD) + (col_g & 31);
    const float* xp = x + (size_t)(rb + row_a) * FIN + kb_a;

    float acc[2][8][4];
#pragma unroll
    for (int mi = 0; mi < 2; mi++)
#pragma unroll
        for (int nb = 0; nb < 8; nb++)
#pragma unroll
            for (int q = 0; q < 4; q++) acc[mi][nb][q] = 0.f;

    float4 va0 = *(const float4*)(xp);
    float4 va1 = *(const float4*)(xp + 4);
    float  vb[8];
#pragma unroll
    for (int i = 0; i < 8; i++) vb[i] = wp[(size_t)(kb_b + i) * DD];

    for (int ch = 0; ch < 16; ch++) {
        __syncthreads();
        {
            float av[8] = {va0.x, va0.y, va0.z, va0.w, va1.x, va1.y, va1.z, va1.w};
#pragma unroll
            for (int i = 0; i < 4; i++) {
                float v0 = av[2*i], v1 = av[2*i+1];
                float h0 = bfround(v0), h1 = bfround(v1);
                sAh[row_a * 12 + (kb_a >> 1) + i] = bfpack(h0, h1);
                sAl[row_a * 12 + (kb_a >> 1) + i] = bfpack(v0 - h0, v1 - h1);
            }
#pragma unroll
            for (int i = 0; i < 4; i++) {
                float v0 = vb[2*i], v1 = vb[2*i+1];
                float h0 = bfround(v0), h1 = bfround(v1);
                sBh[((kb_b >> 1) + i) * 136 + col_b] = bfpack(h0, h1);
                sBl[((kb_b >> 1) + i) * 136 + col_b] = bfpack(v0 - h0, v1 - h1);
            }
        }
        __syncthreads();
        if (ch < 15) {
            const int kc = (ch + 1) * 16;
            va0 = *(const float4*)(xp + kc);
            va1 = *(const float4*)(xp + kc + 4);
#pragma unroll
            for (int i = 0; i < 8; i++) vb[i] = wp[(size_t)(kc + kb_b + i) * DD];
        }
        uint32_t ah[2][4], al[2][4];
#pragma unroll
        for (int mi = 0; mi < 2; mi++) {
            int base = (wy*32 + mi*16 + g) * 12 + tig;
            ah[mi][0] = sAh[base];     ah[mi][1] = sAh[base + 96];
            ah[mi][2] = sAh[base + 4]; ah[mi][3] = sAh[base + 100];
            al[mi][0] = sAl[base];     al[mi][1] = sAl[base + 96];
            al[mi][2] = sAl[base + 4]; al[mi][3] = sAl[base + 100];
        }
#pragma unroll
        for (int nb = 0; nb < 8; nb++) {
            int colb = wx*64 + nb*8 + g;
            uint32_t bh0 = sBh[tig * 136 + colb], bh1 = sBh[(tig + 4) * 136 + colb];
            uint32_t bl0 = sBl[tig * 136 + colb], bl1 = sBl[(tig + 4) * 136 + colb];
#pragma unroll
            for (int mi = 0; mi < 2; mi++) {
                float* c = acc[mi][nb];
                mma_bf16(c, ah[mi][0], ah[mi][1], ah[mi][2], ah[mi][3], bh0, bh1);
                mma_bf16(c, al[mi][0], al[mi][1], al[mi][2], al[mi][3], bh0, bh1);
                mma_bf16(c, ah[mi][0], ah[mi][1], ah[mi][2], ah[mi][3], bl0, bl1);
            }
        }
    }

    __half* wt = (__half*)g_WhT;
#pragma unroll
    for (int mi = 0; mi < 2; mi++) {
        int r0 = rb + wy*32 + mi*16 + g;
        int r1 = r0 + 8;
        int b0 = r0 >> 11, n0 = r0 & (NN-1);
        int b1 = r1 >> 11, n1 = r1 & (NN-1);
#pragma unroll
        for (int nb = 0; nb < 8; nb++) {
            int col = cb + wx*64 + nb*8 + tig*2;
            int h = col >> 5, d = col & 31;
            float* o0 = g_Wh + ((size_t)(b0*HH + h) * NN + n0) * DD + d;
            float* o1 = g_Wh + ((size_t)(b1*HH + h) * NN + n1) * DD + d;
            *(float2*)o0 = make_float2(acc[mi][nb][0], acc[mi][nb][1]);
            *(float2*)o1 = make_float2(acc[mi][nb][2], acc[mi][nb][3]);
            // transposed fp16 copy
            size_t tb0 = ((size_t)(b0*HH + h) * DD + d) * NN;
            size_t tb1 = ((size_t)(b1*HH + h) * DD + d) * NN;
            wt[tb0 + n0]      = __float2half(acc[mi][nb][0]);
            wt[tb0 + NN + n0] = __float2half(acc[mi][nb][1]);
            wt[tb1 + n1]      = __float2half(acc[mi][nb][2]);
            wt[tb1 + NN + n1] = __float2half(acc[mi][nb][3]);
        }
    }
}

// ---------------- kernel 3: fused e/max/exp — one CTA per (b,h) ----------------
__global__ __launch_bounds__(512) void k_ee(const float* __restrict__ a) {
    __shared__ float sA[64];
    __shared__ float sRed[16];
    const int bh = blockIdx.x;
    const int h  = bh & 7;
    const int t  = threadIdx.x;
    if (t < 16) ((float4*)sA)[t] = ((const float4*)(a + h * 64))[t];
    __syncthreads();

    float es[4], ed[4];
    float lmax = -1e30f;
    const float* whb = g_Wh + (size_t)bh * NN * DD;
#pragma unroll
    for (int k = 0; k < 4; k++) {
        const int r = k * 512 + t;
        const float4* wr = (const float4*)(whb + (size_t)r * DD);
        float s0 = 0.f, s1 = 0.f;
#pragma unroll
        for (int q = 0; q < 8; q++) {
            float4 w  = wr[q];
            float4 as = ((const float4*)sA)[q];
            float4 ad = ((const float4*)sA)[8 + q];
            s0 += w.x*as.x + w.y*as.y + w.z*as.z + w.w*as.w;
            s1 += w.x*ad.x + w.y*ad.y + w.z*ad.z + w.w*ad.w;
        }
        es[k] = s0; ed[k] = s1;
        lmax = fmaxf(lmax, s1);
    }
#pragma unroll
    for (int o = 16; o; o >>= 1)
        lmax = fmaxf(lmax, __shfl_xor_sync(0xffffffffu, lmax, o));
    if ((t & 31) == 0) sRed[t >> 5] = lmax;
    __syncthreads();
    float maxE = sRed[0];
#pragma unroll
    for (int i = 1; i < 16; i++) maxE = fmaxf(maxE, sRed[i]);

#pragma unroll
    for (int k = 0; k < 4; k++) {
        const int r = k * 512 + t;
        float sm = es[k] + maxE;
        float m  = fmaxf(sm, 0.2f * sm);
        float dd = ed[k] - maxE;
        g_AI2[(size_t)bh * NN + r] = make_float2(__expf(sm - m), __expf(0.2f * sm - m));
        float E1 = __expf(dd);
        float E2 = __expf(0.2f * dd);
        float o1 = __shfl_down_sync(0xffffffffu, E1, 1);
        float o2 = __shfl_down_sync(0xffffffffu, E2, 1);
        if ((t & 1) == 0) {
            const size_t p = (size_t)bh * (NN/2) + (r >> 1);
            g_E12[p * 2]     = h2pack(E1, o1);
            g_E12[p * 2 + 1] = h2pack(E2, o2);
        }
    }
}

// ---------------- kernel 4: attention — cp.async B, pi-remapped windows ----------------
// Window w of a chunk covers j in {32*tig + 4w + 0..3} (per-thread contiguous j),
// so adjacency = 1 word/row/chunk, E = 1 broadcast LDS.128/window,
// B tiles stream via cp.async from fp16-transposed g_WhT (no cvt, no STS, no regs).
#define BPAD 76                     // words per d-row in sB (pad vs 64)
__global__ __launch_bounds__(256) void k_attn(float* __restrict__ out) {
    __shared__ uint32_t sB[2][32*BPAD];   // fp16x2 words [d][swizzled jpair]
    __shared__ uint32_t sE12[2][128];
    const int t    = threadIdx.x;
    const int lane = t & 31;
    const int wid  = t >> 5;
    const int g    = lane >> 2;
    const int tig  = lane & 3;
    const int bh   = blockIdx.y;
    const int b    = bh >> 3;
    const int h    = bh & 7;
    const int i0   = blockIdx.x * 128;
    const int r0   = i0 + wid * 16 + g;
    const int r1   = r0 + 8;
    const uint32_t ONES2 = 0x3C003C00u;

    const float2 ai0 = g_AI2[(size_t)bh * NN + r0];
    const float2 ai1 = g_AI2[(size_t)bh * NN + r1];
    const uint32_t A1h0 = h2pack(ai0.x, ai0.x), A2h0 = h2pack(ai0.y, ai0.y);
    const uint32_t A1h1 = h2pack(ai1.x, ai1.x), A2h1 = h2pack(ai1.y, ai1.y);
    float acc[16], accs[4];
#pragma unroll
    for (int i = 0; i < 16; i++) acc[i] = 0.f;
#pragma unroll
    for (int i = 0; i < 4; i++) accs[i] = 0.f;

    const __half*   whT  = (const __half*)g_WhT + (size_t)bh * DD * NN;   // [d][j]
    const uint32_t* e12p = g_E12 + (size_t)bh * NN;
    const unsigned* adjp = g_adj + (size_t)b * NW * NN;

    // cp.async staging: thread copies 2 x 16B chunks; id -> (d, jpair-group G)
    const int cp_d0 = (t * 2) >> 4, cp_G0 = (t * 2) & 15;
    const int cp_d1 = (t * 2 + 1) >> 4, cp_G1 = (t * 2 + 1) & 15;
    const uint32_t sbB = (uint32_t)__cvta_generic_to_shared(&sB[0][0]);
    const uint32_t dst0 = sbB + (cp_d0*BPAD + ((cp_G0*4) ^ ((cp_d0 & 3) << 2))) * 4;
    const uint32_t dst1 = sbB + (cp_d1*BPAD + ((cp_G1*4) ^ ((cp_d1 & 3) << 2))) * 4;
    const __half* src0 = whT + (size_t)cp_d0 * NN + cp_G0 * 8;
    const __half* src1 = whT + (size_t)cp_d1 * NN + cp_G1 * 8;
    const int xg    = (g & 3) << 2;              // B LDS swizzle term
    const int bbase = g * BPAD + tig * 16;       // B fragment base (word)
    const int eb    = 32 * tig;                  // E base (word)

    // ---- prologue: stage chunk 0 ----
    CP_ASYNC16(dst0, src0);
    CP_ASYNC16(dst1, src1);
    CP_COMMIT();
    if (t < 32) ((uint4*)sE12[0])[t] = ((const uint4*)e12p)[t];
    unsigned aw0 = adjp[(size_t)tig * NN + r0];
    unsigned aw1 = adjp[(size_t)tig * NN + r1];

    for (int c = 0; c < 16; c++) {
        const int buf = c & 1;
        const int cn  = (c + 1 < 16) ? c + 1 : 0;
        // issue next chunk's B copies
        const uint32_t boffn = (uint32_t)(buf ^ 1) * (32*BPAD*4);
        CP_ASYNC16(dst0 + boffn, src0 + (size_t)cn * 128);
        CP_ASYNC16(dst1 + boffn, src1 + (size_t)cn * 128);
        CP_COMMIT();
        // prefetch next E + adjacency
        uint4 vE = make_uint4(0u,0u,0u,0u);
        if (t < 32) vE = ((const uint4*)(e12p + cn * 128))[t];
        unsigned nw0 = adjp[(size_t)(cn*4 + tig) * NN + r0];
        unsigned nw1 = adjp[(size_t)(cn*4 + tig) * NN + r1];

        CP_WAIT1();            // chunk c's B landed
        __syncthreads();       // visibility of B + previous E staging
        if (t < 32) ((uint4*)sE12[buf ^ 1])[t] = vE;

        const uint32_t* Bf = sB[buf];
#pragma unroll
        for (int w = 0; w < 8; w++) {
            const uint32_t m0a = mask2(aw0, 4*w),     m0b = mask2(aw0, 4*w + 2);
            const uint32_t m1a = mask2(aw1, 4*w),     m1b = mask2(aw1, 4*w + 2);
            uint4 E = *(const uint4*)&sE12[buf][eb + 4*w];
            uint32_t a0 = hmax2(hmul2(A1h0, E.x), hmul2(A2h0, E.y)) & m0a;
            uint32_t a1 = hmax2(hmul2(A1h1, E.x), hmul2(A2h1, E.y)) & m1a;
            uint32_t a2 = hmax2(hmul2(A1h0, E.z), hmul2(A2h0, E.w)) & m0b;
            uint32_t a3 = hmax2(hmul2(A1h1, E.z), hmul2(A2h1, E.w)) & m1b;
            const int boff = bbase + ((2*w) ^ xg);
#pragma unroll
            for (int nb = 0; nb < 4; nb++) {
                uint2 bb = *(const uint2*)&Bf[boff + nb * (8*BPAD)];
                mma_f16(acc + nb * 4, a0, a1, a2, a3, bb.x, bb.y);
            }
            mma_f16(accs, a0, a1, a2, a3, ONES2, ONES2);
        }
        aw0 = nw0; aw1 = nw1;
        __syncthreads();
    }

    // ---- epilogue: normalize by mma rowsums, store ----
    const float inv0 = 1.0f / accs[0];
    const float inv1 = 1.0f / accs[2];
    float* o0 = out + ((size_t)(b * NN + r0)) * (HH * DD) + h * DD + tig * 2;
    float* o1 = out + ((size_t)(b * NN + r1)) * (HH * DD) + h * DD + tig * 2;
#pragma unroll
    for (int nb = 0; nb < 4; nb++) {
        *(float2*)(o0 + nb * 8) = make_float2(acc[nb*4 + 0] * inv0, acc[nb*4 + 1] * inv0);
        *(float2*)(o1 + nb * 8) = make_float2(acc[nb*4 + 2] * inv1, acc[nb*4 + 3] * inv1);
    }
}

// ---------------- launch ----------------
extern "C" void kernel_launch(void* const* d_in, const int* in_sizes, int n_in,
                              void* d_out, int out_size) {
    const float* x   = (const float*)d_in[0];
    const int*   adj = (const int*)  d_in[1];
    const float* W   = (const float*)d_in[2];
    const float* a   = (const float*)d_in[3];
    float* out = (float*)d_out;

    k_pack <<<2048, 256>>>(adj);
    k_gemm1<<<dim3(2, 64), 256>>>(x, W);
    k_ee   <<<BB*HH, 512>>>(a);
    k_attn <<<dim3(NN/128, BB*HH), 256>>>(out);
}

// round 17
// speedup vs baseline: 1.6068x; 1.6068x over previous
#include <cuda_runtime.h>
#include <cuda_bf16.h>
#include <cuda_fp16.h>
#include <cstdint>

#define BB  4
#define NN  2048
#define FIN 256
#define HH  8
#define DD  32
#define NW  (NN/32)   // 64 adj words per row
#define CHW 2048      // uint32 words per 128-j fragment-image chunk

// ---------------- device scratch (no allocations allowed) ----------------
__device__ float    g_Wh [BB*HH*NN*DD];      // f32 [b][h][n][d] (k_ee)
__device__ uint32_t g_WhH[BB*HH*NN*16];      // fp16 pairs-along-d [bh][n][d/2] (k_frag src)
__device__ uint32_t g_WhF[BB*HH*16*CHW];     // fragment-order fp16 image (k_attn B)
__device__ float2   g_AI2[BB*HH*NN];         // (A1, A2) per row i
__device__ uint32_t g_E12[BB*HH*NN];         // per j-pair: {E1 f16x2, E2 f16x2} interleaved
__device__ unsigned g_adj[BB*NN*NW];         // packed adjacency bits, TRANSPOSED [b][jw][i]

// ---------------- helpers ----------------
__device__ __forceinline__ void mma_bf16(float* c,
                                         uint32_t a0, uint32_t a1, uint32_t a2, uint32_t a3,
                                         uint32_t b0, uint32_t b1) {
    asm volatile(
        "mma.sync.aligned.m16n8k16.row.col.f32.bf16.bf16.f32 "
        "{%0,%1,%2,%3}, {%4,%5,%6,%7}, {%8,%9}, {%0,%1,%2,%3};"
        : "+f"(c[0]), "+f"(c[1]), "+f"(c[2]), "+f"(c[3])
        : "r"(a0), "r"(a1), "r"(a2), "r"(a3), "r"(b0), "r"(b1));
}
__device__ __forceinline__ void mma_f16(float* c,
                                        uint32_t a0, uint32_t a1, uint32_t a2, uint32_t a3,
                                        uint32_t b0, uint32_t b1) {
    asm volatile(
        "mma.sync.aligned.m16n8k16.row.col.f32.f16.f16.f32 "
        "{%0,%1,%2,%3}, {%4,%5,%6,%7}, {%8,%9}, {%0,%1,%2,%3};"
        : "+f"(c[0]), "+f"(c[1]), "+f"(c[2]), "+f"(c[3])
        : "r"(a0), "r"(a1), "r"(a2), "r"(a3), "r"(b0), "r"(b1));
}
__device__ __forceinline__ uint32_t bfpack(float lo, float hi) {
    uint32_t r;
    asm("cvt.rn.bf16x2.f32 %0, %1, %2;" : "=r"(r) : "f"(hi), "f"(lo));
    return r;
}
__device__ __forceinline__ uint32_t h2pack(float lo, float hi) {
    uint32_t r;
    asm("cvt.rn.f16x2.f32 %0, %1, %2;" : "=r"(r) : "f"(hi), "f"(lo));
    return r;
}
__device__ __forceinline__ float bfround(float v) {
    return __bfloat162float(__float2bfloat16(v));
}
__device__ __forceinline__ uint32_t hmul2(uint32_t a, uint32_t b) {
    uint32_t r;
    asm("mul.f16x2 %0, %1, %2;" : "=r"(r) : "r"(a), "r"(b));
    return r;
}
__device__ __forceinline__ uint32_t hmax2(uint32_t a, uint32_t b) {
    uint32_t r;
    asm("max.f16x2 %0, %1, %2;" : "=r"(r) : "r"(a), "r"(b));
    return r;
}
// mask word for adjacency bits k,k+1: 0xFFFF per set halfword (PROVEN in R14)
__device__ __forceinline__ uint32_t mask2(uint32_t word, int k) {
    uint32_t t0, t1;
    asm("bfe.u32 %0, %1, %2, 1;" : "=r"(t0) : "r"(word), "r"(k));
    asm("bfe.u32 %0, %1, %2, 1;" : "=r"(t1) : "r"(word), "r"(k + 1));
    return t0 * 0x0000FFFFu + t1 * 0xFFFF0000u;
}
#define CP_ASYNC16(dst32, src) \
    asm volatile("cp.async.cg.shared.global [%0], [%1], 16;" :: "r"(dst32), "l"(src) : "memory")
#define CP_COMMIT() asm volatile("cp.async.commit_group;" ::: "memory")
#define CP_WAIT1()  asm volatile("cp.async.wait_group 1;" ::: "memory")

// ---------------- kernel 1: pack adjacency to bits (transposed) ----------------
__global__ __launch_bounds__(256) void k_pack(const int* __restrict__ adj) {
    const int nwarps = (gridDim.x * blockDim.x) >> 5;
    const int wid    = (blockIdx.x * blockDim.x + threadIdx.x) >> 5;
    const int lane   = threadIdx.x & 31;
    const int total  = BB*NN*NW;
    for (int w = wid; w < total; w += nwarps) {
        int v = adj[(size_t)w * 32 + lane];
        unsigned m = __ballot_sync(0xffffffffu, v != 0);
        if (lane == 0) {
            int b  = w / (NN*NW);
            int r  = w - b * (NN*NW);
            int i  = r / NW;
            int jw = r - i * NW;
            g_adj[((size_t)b * NW + jw) * NN + i] = m;
        }
    }
}

// ---------------- kernel 2: Wh = x @ W via 3xBF16 mma.sync (near-fp32) ----------------
__global__ __launch_bounds__(256) void k_gemm1(const float* __restrict__ x,
                                               const float* __restrict__ W) {
    __shared__ uint32_t sAh[128*12], sAl[128*12];
    __shared__ uint32_t sBh[8*136],  sBl[8*136];
    const int t    = threadIdx.x;
    const int lane = t & 31;
    const int wid  = t >> 5;
    const int g    = lane >> 2;
    const int tig  = lane & 3;
    const int wy   = wid & 3;
    const int wx   = wid >> 2;
    const int rb   = blockIdx.y * 128;
    const int cb   = blockIdx.x * 128;

    const int row_a = t >> 1;
    const int kb_a  = (t & 1) * 8;
    const int col_b = t & 127;
    const int kb_b  = (t >> 7) * 8;
    const int col_g = cb + col_b;
    const float* wp = W + (size_t)(col_g >> 5) * (FIN*DD) + (col_g & 31);
    const float* xp = x + (size_t)(rb + row_a) * FIN + kb_a;

    float acc[2][8][4];
#pragma unroll
    for (int mi = 0; mi < 2; mi++)
#pragma unroll
        for (int nb = 0; nb < 8; nb++)
#pragma unroll
            for (int q = 0; q < 4; q++) acc[mi][nb][q] = 0.f;

    float4 va0 = *(const float4*)(xp);
    float4 va1 = *(const float4*)(xp + 4);
    float  vb[8];
#pragma unroll
    for (int i = 0; i < 8; i++) vb[i] = wp[(size_t)(kb_b + i) * DD];

    for (int ch = 0; ch < 16; ch++) {
        __syncthreads();
        {
            float av[8] = {va0.x, va0.y, va0.z, va0.w, va1.x, va1.y, va1.z, va1.w};
#pragma unroll
            for (int i = 0; i < 4; i++) {
                float v0 = av[2*i], v1 = av[2*i+1];
                float h0 = bfround(v0), h1 = bfround(v1);
                sAh[row_a * 12 + (kb_a >> 1) + i] = bfpack(h0, h1);
                sAl[row_a * 12 + (kb_a >> 1) + i] = bfpack(v0 - h0, v1 - h1);
            }
#pragma unroll
            for (int i = 0; i < 4; i++) {
                float v0 = vb[2*i], v1 = vb[2*i+1];
                float h0 = bfround(v0), h1 = bfround(v1);
                sBh[((kb_b >> 1) + i) * 136 + col_b] = bfpack(h0, h1);
                sBl[((kb_b >> 1) + i) * 136 + col_b] = bfpack(v0 - h0, v1 - h1);
            }
        }
        __syncthreads();
        if (ch < 15) {
            const int kc = (ch + 1) * 16;
            va0 = *(const float4*)(xp + kc);
            va1 = *(const float4*)(xp + kc + 4);
#pragma unroll
            for (int i = 0; i < 8; i++) vb[i] = wp[(size_t)(kc + kb_b + i) * DD];
        }
        uint32_t ah[2][4], al[2][4];
#pragma unroll
        for (int mi = 0; mi < 2; mi++) {
            int base = (wy*32 + mi*16 + g) * 12 + tig;
            ah[mi][0] = sAh[base];     ah[mi][1] = sAh[base + 96];
            ah[mi][2] = sAh[base + 4]; ah[mi][3] = sAh[base + 100];
            al[mi][0] = sAl[base];     al[mi][1] = sAl[base + 96];
            al[mi][2] = sAl[base + 4]; al[mi][3] = sAl[base + 100];
        }
#pragma unroll
        for (int nb = 0; nb < 8; nb++) {
            int colb = wx*64 + nb*8 + g;
            uint32_t bh0 = sBh[tig * 136 + colb], bh1 = sBh[(tig + 4) * 136 + colb];
            uint32_t bl0 = sBl[tig * 136 + colb], bl1 = sBl[(tig + 4) * 136 + colb];
#pragma unroll
            for (int mi = 0; mi < 2; mi++) {
                float* c = acc[mi][nb];
                mma_bf16(c, ah[mi][0], ah[mi][1], ah[mi][2], ah[mi][3], bh0, bh1);
                mma_bf16(c, al[mi][0], al[mi][1], al[mi][2], al[mi][3], bh0, bh1);
                mma_bf16(c, ah[mi][0], ah[mi][1], ah[mi][2], ah[mi][3], bl0, bl1);
            }
        }
    }

#pragma unroll
    for (int mi = 0; mi < 2; mi++) {
        int r0 = rb + wy*32 + mi*16 + g;
        int r1 = r0 + 8;
        int b0 = r0 >> 11, n0 = r0 & (NN-1);
        int b1 = r1 >> 11, n1 = r1 & (NN-1);
#pragma unroll
        for (int nb = 0; nb < 8; nb++) {
            int col = cb + wx*64 + nb*8 + tig*2;
            int h = col >> 5, d = col & 31;
            float* o0 = g_Wh + ((size_t)(b0*HH + h) * NN + n0) * DD + d;
            float* o1 = g_Wh + ((size_t)(b1*HH + h) * NN + n1) * DD + d;
            *(float2*)o0 = make_float2(acc[mi][nb][0], acc[mi][nb][1]);
            *(float2*)o1 = make_float2(acc[mi][nb][2], acc[mi][nb][3]);
            const int dp = (nb & 3) * 4 + tig;           // (d&31)>>1
            g_WhH[((size_t)(b0*HH + h) * NN + n0) * 16 + dp] = h2pack(acc[mi][nb][0], acc[mi][nb][1]);
            g_WhH[((size_t)(b1*HH + h) * NN + n1) * 16 + dp] = h2pack(acc[mi][nb][2], acc[mi][nb][3]);
        }
    }
}

// ---------------- kernel 3: fused e/max/exp — one CTA per (b,h) ----------------
__global__ __launch_bounds__(512) void k_ee(const float* __restrict__ a) {
    __shared__ float sA[64];
    __shared__ float sRed[16];
    const int bh = blockIdx.x;
    const int h  = bh & 7;
    const int t  = threadIdx.x;
    if (t < 16) ((float4*)sA)[t] = ((const float4*)(a + h * 64))[t];
    __syncthreads();

    float es[4], ed[4];
    float lmax = -1e30f;
    const float* whb = g_Wh + (size_t)bh * NN * DD;
#pragma unroll
    for (int k = 0; k < 4; k++) {
        const int r = k * 512 + t;
        const float4* wr = (const float4*)(whb + (size_t)r * DD);
        float s0 = 0.f, s1 = 0.f;
#pragma unroll
        for (int q = 0; q < 8; q++) {
            float4 w  = wr[q];
            float4 as = ((const float4*)sA)[q];
            float4 ad = ((const float4*)sA)[8 + q];
            s0 += w.x*as.x + w.y*as.y + w.z*as.z + w.w*as.w;
            s1 += w.x*ad.x + w.y*ad.y + w.z*ad.z + w.w*ad.w;
        }
        es[k] = s0; ed[k] = s1;
        lmax = fmaxf(lmax, s1);
    }
#pragma unroll
    for (int o = 16; o; o >>= 1)
        lmax = fmaxf(lmax, __shfl_xor_sync(0xffffffffu, lmax, o));
    if ((t & 31) == 0) sRed[t >> 5] = lmax;
    __syncthreads();
    float maxE = sRed[0];
#pragma unroll
    for (int i = 1; i < 16; i++) maxE = fmaxf(maxE, sRed[i]);

#pragma unroll
    for (int k = 0; k < 4; k++) {
        const int r = k * 512 + t;
        float sm = es[k] + maxE;
        float m  = fmaxf(sm, 0.2f * sm);
        float dd = ed[k] - maxE;
        g_AI2[(size_t)bh * NN + r] = make_float2(__expf(sm - m), __expf(0.2f * sm - m));
        float E1 = __expf(dd);
        float E2 = __expf(0.2f * dd);
        float o1 = __shfl_down_sync(0xffffffffu, E1, 1);
        float o2 = __shfl_down_sync(0xffffffffu, E2, 1);
        if ((t & 1) == 0) {
            const size_t p = (size_t)bh * (NN/2) + (r >> 1);
            g_E12[p * 2]     = h2pack(E1, o1);
            g_E12[p * 2 + 1] = h2pack(E2, o2);
        }
    }
}

// ---------------- kernel 3.5: build fragment-order fp16 B image ----------------
// Word widx = (w*4+nb)*64 + z, z = (g*8+tig*2+phi)^(nb<<3), holds fp16x2
// (Wh[d][j0], Wh[d][j0+1]) with d = nb*8+g, j0 = 32*tig + 4*w + 2*phi.
__global__ __launch_bounds__(128) void k_frag() {
    __shared__ uint32_t sH[128*20];       // [n][d-pair] padded stride 20
    const int t    = threadIdx.x;
    const uint32_t* src = g_WhH + (size_t)blockIdx.x * (128*16);
    uint32_t*       dst = g_WhF + (size_t)blockIdx.x * CHW;

#pragma unroll
    for (int m = 0; m < 4; m++) {
        uint4 v = ((const uint4*)src)[m * 128 + t];
        int f = (m * 128 + t) * 4;
        int n = f >> 4, dp = f & 15;
        *(uint4*)&sH[n * 20 + dp] = v;
    }
    __syncthreads();

#pragma unroll
    for (int q = 0; q < 4; q++) {
        uint32_t ow[4];
#pragma unroll
        for (int e = 0; e < 4; e++) {
            int widx = (q * 128 + t) * 4 + e;
            int blk = widx >> 6;
            int w   = blk >> 2, nb = blk & 3;
            int z   = widx & 63;
            int ll  = z ^ (nb << 3);
            int g2  = ll >> 3, tg = (ll >> 1) & 3, phi = ll & 1;
            int d   = nb * 8 + g2;
            int j0  = tg * 32 + w * 4 + phi * 2;
            uint32_t v0 = sH[j0 * 20 + (d >> 1)];
            uint32_t v1 = sH[(j0 + 1) * 20 + (d >> 1)];
            ow[e] = __byte_perm(v0, v1, (d & 1) ? 0x7632 : 0x5410);
        }
        ((uint4*)dst)[q * 128 + t] = make_uint4(ow[0], ow[1], ow[2], ow[3]);
    }
}

// ---------------- kernel 4: attention — cp.async linear B, proven bfe masks ----------------
__global__ __launch_bounds__(256) void k_attn(float* __restrict__ out) {
    __shared__ __align__(16) uint32_t sB[2][CHW];   // fragment image, 2 x 8KB
    __shared__ __align__(16) uint32_t sE[2][144];   // [tig pad 36]{E1,E2 per jpair}
    const int t    = threadIdx.x;
    const int lane = t & 31;
    const int g    = lane >> 2;
    const int tig  = lane & 3;
    const int bh   = blockIdx.y;
    const int b    = bh >> 3;
    const int h    = bh & 7;
    const int i0   = blockIdx.x * 128;
    const int r0   = i0 + (t >> 5) * 16 + g;
    const int r1   = r0 + 8;
    const uint32_t ONES2 = 0x3C003C00u;

    const float2 ai0 = g_AI2[(size_t)bh * NN + r0];
    const float2 ai1 = g_AI2[(size_t)bh * NN + r1];
    const uint32_t A1h0 = h2pack(ai0.x, ai0.x), A2h0 = h2pack(ai0.y, ai0.y);
    const uint32_t A1h1 = h2pack(ai1.x, ai1.x), A2h1 = h2pack(ai1.y, ai1.y);
    float acc[16], accs[4];
#pragma unroll
    for (int i = 0; i < 16; i++) acc[i] = 0.f;
#pragma unroll
    for (int i = 0; i < 4; i++) accs[i] = 0.f;

    const uint32_t* whF  = g_WhF + (size_t)bh * 16 * CHW;
    const uint32_t* e12p = g_E12 + (size_t)bh * NN;
    const unsigned* adjp = g_adj + (size_t)b * NW * NN;

    const uint32_t sbB  = (uint32_t)__cvta_generic_to_shared(&sB[0][0]);
    const uint32_t dstB = sbB + (uint32_t)t * 32;
    const int eDst = (t >> 3) * 36 + (t & 7) * 4;   // valid for t<32
    const int eRd  = tig * 36;

    // ---- prologue: stage chunk 0 ----
    CP_ASYNC16(dstB,      whF + t * 8);
    CP_ASYNC16(dstB + 16, whF + t * 8 + 4);
    CP_COMMIT();
    if (t < 32) *(uint4*)&sE[0][eDst] = ((const uint4*)e12p)[t];
    unsigned aw0 = adjp[(size_t)tig * NN + r0];
    unsigned aw1 = adjp[(size_t)tig * NN + r1];

    for (int c = 0; c < 16; c++) {
        const int buf = c & 1;
        const int cn  = (c + 1 < 16) ? c + 1 : 0;
        const uint32_t bofn = (uint32_t)(buf ^ 1) * (CHW * 4);
        CP_ASYNC16(dstB + bofn,      whF + cn * CHW + t * 8);
        CP_ASYNC16(dstB + bofn + 16, whF + cn * CHW + t * 8 + 4);
        CP_COMMIT();
        uint4 vE = make_uint4(0u, 0u, 0u, 0u);
        if (t < 32) vE = ((const uint4*)(e12p + cn * 128))[t];
        unsigned nw0 = adjp[(size_t)(cn * 4 + tig) * NN + r0];
        unsigned nw1 = adjp[(size_t)(cn * 4 + tig) * NN + r1];

        CP_WAIT1();
        __syncthreads();
        if (t < 32) *(uint4*)&sE[buf ^ 1][eDst] = vE;

        const uint32_t* Bf = sB[buf];
#pragma unroll
        for (int w = 0; w < 8; w++) {
            const uint32_t m0a = mask2(aw0, 4*w), m0b = mask2(aw0, 4*w + 2);
            const uint32_t m1a = mask2(aw1, 4*w), m1b = mask2(aw1, 4*w + 2);
            uint4 E = *(const uint4*)&sE[buf][eRd + 4 * w];   // {E1,E2,E1',E2'}
            uint32_t a0 = hmax2(hmul2(A1h0, E.x), hmul2(A2h0, E.y)) & m0a;
            uint32_t a1 = hmax2(hmul2(A1h1, E.x), hmul2(A2h1, E.y)) & m1a;
            uint32_t a2 = hmax2(hmul2(A1h0, E.z), hmul2(A2h0, E.w)) & m0b;
            uint32_t a3 = hmax2(hmul2(A1h1, E.z), hmul2(A2h1, E.w)) & m1b;
#pragma unroll
            for (int nb = 0; nb < 4; nb++) {
                uint2 bb = *(const uint2*)&Bf[(w*4 + nb)*64 + ((lane*2) ^ (nb << 3))];
                mma_f16(acc + nb * 4, a0, a1, a2, a3, bb.x, bb.y);
            }
            mma_f16(accs, a0, a1, a2, a3, ONES2, ONES2);
        }
        aw0 = nw0; aw1 = nw1;
        __syncthreads();
    }

    // ---- epilogue: normalize by mma rowsums, store ----
    const float inv0 = 1.0f / accs[0];
    const float inv1 = 1.0f / accs[2];
    float* o0 = out + ((size_t)(b * NN + r0)) * (HH * DD) + h * DD + tig * 2;
    float* o1 = out + ((size_t)(b * NN + r1)) * (HH * DD) + h * DD + tig * 2;
#pragma unroll
    for (int nb = 0; nb < 4; nb++) {
        *(float2*)(o0 + nb * 8) = make_float2(acc[nb*4 + 0] * inv0, acc[nb*4 + 1] * inv0);
        *(float2*)(o1 + nb * 8) = make_float2(acc[nb*4 + 2] * inv1, acc[nb*4 + 3] * inv1);
    }
}

// ---------------- launch ----------------
extern "C" void kernel_launch(void* const* d_in, const int* in_sizes, int n_in,
                              void* d_out, int out_size) {
    const float* x   = (const float*)d_in[0];
    const int*   adj = (const int*)  d_in[1];
    const float* W   = (const float*)d_in[2];
    const float* a   = (const float*)d_in[3];
    float* out = (float*)d_out;

    k_pack <<<2048, 256>>>(adj);
    k_gemm1<<<dim3(2, 64), 256>>>(x, W);
    k_ee   <<<BB*HH, 512>>>(a);
    k_frag <<<BB*HH*16, 128>>>();
    k_attn <<<dim3(NN/128, BB*HH), 256>>>(out);
}